// round 3
// baseline (speedup 1.0000x reference)
#include <cuda_runtime.h>
#include <math.h>

// Problem constants
#define BB 4
#define SS 1024
#define DD 1024
#define BS (BB*SS)          // 4096 rows total
#define ELEMS ((size_t)BB*SS*DD)   // 4194304

// ---------------- scratch (no allocation allowed) ----------------
__device__ float g_Q[ELEMS];
__device__ float g_K[ELEMS];
__device__ float g_V[ELEMS];
__device__ float g_AV[ELEMS];
__device__ float g_Sq[BS];
__device__ float g_Tq[BS];
__device__ float g_Sk[BS];
__device__ float g_Tk[BS];

// ---------------- per-row entropy stats ----------------
// Sq[r] = sum_{m<8} exp(tanh(q[r,m])),  Tq[r] = sum x*exp(x)
__global__ void stats_kernel(const float* __restrict__ q, const float* __restrict__ k,
                             float* __restrict__ Sq, float* __restrict__ Tq,
                             float* __restrict__ Sk, float* __restrict__ Tk)
{
    int r = blockIdx.x * blockDim.x + threadIdx.x;
    if (r >= BS) return;
    float s = 0.f, t = 0.f;
    #pragma unroll
    for (int m = 0; m < 8; m++) {
        float x = tanhf(q[(size_t)r * DD + m]);
        float e = expf(x);
        s += e; t += x * e;
    }
    Sq[r] = s; Tq[r] = t;
    s = 0.f; t = 0.f;
    #pragma unroll
    for (int m = 0; m < 8; m++) {
        float x = tanhf(k[(size_t)r * DD + m]);
        float e = expf(x);
        s += e; t += x * e;
    }
    Sk[r] = s; Tk[r] = t;
}

// ---------------- tiled fp32 GEMM ----------------
// C[M,N] = A[M,K](row-major, lda=K) * B' + bias
//   BT=true : B is [N,K] row-major (ldb=K) -> C = A * B^T   (torch Linear / Q@K^T)
//   BT=false: B is [K,N] row-major (ldb=N) -> C = A * B     (attn @ V)
// ldc = N. blockIdx.z batches with given strides.
#define Bb_M 128
#define Bb_N 128
#define Bb_K 16
#define PADs 4

template<bool BT>
__global__ __launch_bounds__(256, 2)
void gemm_kernel(const float* __restrict__ A, const float* __restrict__ B,
                 const float* __restrict__ bias, float* __restrict__ C,
                 int M, int N, int K,
                 long strideA, long strideB, long strideC)
{
    __shared__ float As[Bb_K][Bb_M + PADs];
    __shared__ float Bs[Bb_K][Bb_N + PADs];

    const int tid = threadIdx.x;
    const int tx = tid & 15;        // 0..15 -> col group
    const int ty = tid >> 4;        // 0..15 -> row group
    const int rowBase = blockIdx.y * Bb_M;
    const int colBase = blockIdx.x * Bb_N;

    const float* Ab = A + (long)blockIdx.z * strideA;
    const float* Bbp = B + (long)blockIdx.z * strideB;
    float* Cb = C + (long)blockIdx.z * strideC;

    float acc[8][8];
    #pragma unroll
    for (int i = 0; i < 8; i++)
        #pragma unroll
        for (int j = 0; j < 8; j++) acc[i][j] = 0.f;

    for (int k0 = 0; k0 < K; k0 += Bb_K) {
        // A tile: 128 rows x 16 k, store k-major (transposed)
        #pragma unroll
        for (int it = 0; it < 2; it++) {
            int lin = tid + it * 256;       // 0..511
            int r  = lin >> 2;              // 0..127
            int kq = (lin & 3) * 4;
            float4 v = *reinterpret_cast<const float4*>(&Ab[(long)(rowBase + r) * K + k0 + kq]);
            As[kq + 0][r] = v.x; As[kq + 1][r] = v.y;
            As[kq + 2][r] = v.z; As[kq + 3][r] = v.w;
        }
        if constexpr (BT) {
            #pragma unroll
            for (int it = 0; it < 2; it++) {
                int lin = tid + it * 256;
                int r  = lin >> 2;          // col index 0..127
                int kq = (lin & 3) * 4;
                float4 v = *reinterpret_cast<const float4*>(&Bbp[(long)(colBase + r) * K + k0 + kq]);
                Bs[kq + 0][r] = v.x; Bs[kq + 1][r] = v.y;
                Bs[kq + 2][r] = v.z; Bs[kq + 3][r] = v.w;
            }
        } else {
            #pragma unroll
            for (int it = 0; it < 2; it++) {
                int lin = tid + it * 256;
                int kr = lin >> 5;          // 0..15
                int nq = (lin & 31) * 4;
                float4 v = *reinterpret_cast<const float4*>(&Bbp[(long)(k0 + kr) * N + colBase + nq]);
                *reinterpret_cast<float4*>(&Bs[kr][nq]) = v;
            }
        }
        __syncthreads();

        #pragma unroll
        for (int kk = 0; kk < Bb_K; kk++) {
            float a[8], b[8];
            #pragma unroll
            for (int i = 0; i < 8; i++) a[i] = As[kk][ty * 8 + i];
            #pragma unroll
            for (int j = 0; j < 8; j++) b[j] = Bs[kk][tx * 8 + j];
            #pragma unroll
            for (int i = 0; i < 8; i++)
                #pragma unroll
                for (int j = 0; j < 8; j++)
                    acc[i][j] += a[i] * b[j];
        }
        __syncthreads();
    }

    #pragma unroll
    for (int i = 0; i < 8; i++) {
        int r = rowBase + ty * 8 + i;
        #pragma unroll
        for (int j = 0; j < 8; j += 4) {
            int c = colBase + tx * 8 + j;
            float4 v;
            v.x = acc[i][j + 0] + (bias ? bias[c + 0] : 0.f);
            v.y = acc[i][j + 1] + (bias ? bias[c + 1] : 0.f);
            v.z = acc[i][j + 2] + (bias ? bias[c + 2] : 0.f);
            v.w = acc[i][j + 3] + (bias ? bias[c + 3] : 0.f);
            *reinterpret_cast<float4*>(&Cb[(long)r * N + c]) = v;
        }
    }
}

// ---------------- fused combined + softmax ----------------
// In-place on attn buffer holding raw QK^T scores.
// combined = 0.7*score/128 + 0.3*(log(Z) - (Tq+Tk)/Z - 1.6e-7), Z = Sq_i + Sk_j
__global__ __launch_bounds__(256)
void softmax_kernel(float* __restrict__ attn,
                    const float* __restrict__ Sq, const float* __restrict__ Tq,
                    const float* __restrict__ Sk, const float* __restrict__ Tk)
{
    const int row = blockIdx.x;      // 0..4095
    const int b = row >> 10;
    float* a = attn + (size_t)row * SS;
    const float sq = Sq[row], tq = Tq[row];
    const float* skb = Sk + b * SS;
    const float* tkb = Tk + b * SS;
    const int tid = threadIdx.x;

    float c[4];
    float mx = -1e30f;
    #pragma unroll
    for (int u = 0; u < 4; u++) {
        int j = tid + u * 256;
        float Z = sq + skb[j];
        float ent = __logf(Z) - (tq + tkb[j]) / Z - 1.6e-7f;
        float v = 0.7f * (a[j] * (1.0f / 128.0f)) + 0.3f * ent;
        c[u] = v;
        mx = fmaxf(mx, v);
    }

    __shared__ float red[256];
    red[tid] = mx;
    __syncthreads();
    for (int s = 128; s > 0; s >>= 1) {
        if (tid < s) red[tid] = fmaxf(red[tid], red[tid + s]);
        __syncthreads();
    }
    mx = red[0];
    __syncthreads();

    float sum = 0.f;
    #pragma unroll
    for (int u = 0; u < 4; u++) {
        c[u] = __expf(c[u] - mx);
        sum += c[u];
    }
    red[tid] = sum;
    __syncthreads();
    for (int s = 128; s > 0; s >>= 1) {
        if (tid < s) red[tid] += red[tid + s];
        __syncthreads();
    }
    const float inv = 1.0f / red[0];

    #pragma unroll
    for (int u = 0; u < 4; u++) {
        int j = tid + u * 256;
        a[j] = c[u] * inv;
    }
}

// ---------------- launch ----------------
extern "C" void kernel_launch(void* const* d_in, const int* in_sizes, int n_in,
                              void* d_out, int out_size)
{
    const float* query = (const float*)d_in[0];
    const float* key   = (const float*)d_in[1];
    const float* value = (const float*)d_in[2];
    const float* Wq = (const float*)d_in[3];
    const float* bq = (const float*)d_in[4];
    const float* Wk = (const float*)d_in[5];
    const float* bk = (const float*)d_in[6];
    const float* Wv = (const float*)d_in[7];
    const float* bv = (const float*)d_in[8];
    const float* Wo = (const float*)d_in[9];
    const float* bo = (const float*)d_in[10];

    float* out  = (float*)d_out;            // [B,S,D]
    float* attn = out + ELEMS;              // [B,S,S]

    float *pQ, *pK, *pV, *pAV, *pSq, *pTq, *pSk, *pTk;
    cudaGetSymbolAddress((void**)&pQ,  g_Q);
    cudaGetSymbolAddress((void**)&pK,  g_K);
    cudaGetSymbolAddress((void**)&pV,  g_V);
    cudaGetSymbolAddress((void**)&pAV, g_AV);
    cudaGetSymbolAddress((void**)&pSq, g_Sq);
    cudaGetSymbolAddress((void**)&pTq, g_Tq);
    cudaGetSymbolAddress((void**)&pSk, g_Sk);
    cudaGetSymbolAddress((void**)&pTk, g_Tk);

    // 1) entropy stats
    stats_kernel<<<BS / 256, 256>>>(query, key, pSq, pTq, pSk, pTk);

    // 2) projections: Y = X @ W^T + b   (M=4096, N=1024, K=1024)
    dim3 gp(DD / Bb_N, BS / Bb_M, 1);
    gemm_kernel<true><<<gp, 256>>>(query, Wq, bq, pQ, BS, DD, DD, 0, 0, 0);
    gemm_kernel<true><<<gp, 256>>>(key,   Wk, bk, pK, BS, DD, DD, 0, 0, 0);
    gemm_kernel<true><<<gp, 256>>>(value, Wv, bv, pV, BS, DD, DD, 0, 0, 0);

    // 3) raw scores S = Q @ K^T per batch -> into attn buffer
    dim3 gs(SS / Bb_N, SS / Bb_M, BB);
    const long bstr = (long)SS * SS;   // == S*D here (1024*1024)
    gemm_kernel<true><<<gs, 256>>>(pQ, pK, nullptr, attn, SS, SS, DD, bstr, bstr, bstr);

    // 4) fused combined + softmax (in place)
    softmax_kernel<<<BS, 256>>>(attn, pSq, pTq, pSk, pTk);

    // 5) AV = attn @ V per batch
    gemm_kernel<false><<<gs, 256>>>(attn, pV, nullptr, pAV, SS, DD, SS, bstr, bstr, bstr);

    // 6) output = AV @ Wo^T + bo
    gemm_kernel<true><<<gp, 256>>>(pAV, Wo, bo, out, BS, DD, DD, 0, 0, 0);
}

// round 7
// speedup vs baseline: 1.9826x; 1.9826x over previous
#include <cuda_runtime.h>
#include <cuda_bf16.h>
#include <cstdint>
#include <math.h>

// Problem constants
#define BB 4
#define SS 1024
#define DD 1024
#define BS (BB*SS)                  // 4096 rows total
#define ELEMS ((size_t)BB*SS*DD)    // 4194304  (== B*S*S too)

// ============================================================================
// GEMM tiling
// ============================================================================
#define BM 128
#define BN 128
#define BK 32
#define ASTRIDE 40                      // bf16 elems per smem row (80 bytes)
#define TILE_B (128*ASTRIDE*2)          // 10240 bytes per tile
#define STAGE_B (4*TILE_B)              // Ah, Al, Bh, Bl
#define SMEM_REQ (2*STAGE_B)            // double buffered: 81920 bytes

__device__ __forceinline__ uint32_t smem_to_u32(const void* smem_ptr) {
    uint32_t addr;
    asm("{ .reg .u64 tmp; cvta.to.shared.u64 tmp, %1; cvt.u32.u64 %0, tmp; }"
        : "=r"(addr) : "l"(smem_ptr));
    return addr;
}

__device__ __forceinline__ void ldsm4(uint32_t* r, uint32_t addr) {
    asm volatile("ldmatrix.sync.aligned.m8n8.x4.shared.b16 {%0,%1,%2,%3}, [%4];"
                 : "=r"(r[0]), "=r"(r[1]), "=r"(r[2]), "=r"(r[3]) : "r"(addr));
}
__device__ __forceinline__ void ldsm2(uint32_t* r, uint32_t addr) {
    asm volatile("ldmatrix.sync.aligned.m8n8.x2.shared.b16 {%0,%1}, [%2];"
                 : "=r"(r[0]), "=r"(r[1]) : "r"(addr));
}
__device__ __forceinline__ void mma_bf16(float* c, const uint32_t* a, const uint32_t* b) {
    asm volatile(
        "mma.sync.aligned.m16n8k16.row.col.f32.bf16.bf16.f32 "
        "{%0,%1,%2,%3}, {%4,%5,%6,%7}, {%8,%9}, {%0,%1,%2,%3};"
        : "+f"(c[0]), "+f"(c[1]), "+f"(c[2]), "+f"(c[3])
        : "r"(a[0]), "r"(a[1]), "r"(a[2]), "r"(a[3]), "r"(b[0]), "r"(b[1]));
}
__device__ __forceinline__ void sts16(uint32_t addr, uint4 v) {
    asm volatile("st.shared.v4.b32 [%0], {%1,%2,%3,%4};"
                 :: "r"(addr), "r"(v.x), "r"(v.y), "r"(v.z), "r"(v.w));
}

// ============================================================================
// Scratch (no allocation allowed)
// ============================================================================
__device__ __nv_bfloat16 g_qih[ELEMS], g_qil[ELEMS];
__device__ __nv_bfloat16 g_kih[ELEMS], g_kil[ELEMS];
__device__ __nv_bfloat16 g_vih[ELEMS], g_vil[ELEMS];
__device__ __nv_bfloat16 g_Wqh[DD*DD], g_Wql[DD*DD];
__device__ __nv_bfloat16 g_Wkh[DD*DD], g_Wkl[DD*DD];
__device__ __nv_bfloat16 g_Wvh[DD*DD], g_Wvl[DD*DD];
__device__ __nv_bfloat16 g_Woh[DD*DD], g_Wol[DD*DD];
__device__ __nv_bfloat16 g_Qh[ELEMS],  g_Ql[ELEMS];
__device__ __nv_bfloat16 g_Kh[ELEMS],  g_Kl[ELEMS];
__device__ __nv_bfloat16 g_Vh[ELEMS],  g_Vl[ELEMS];
__device__ __nv_bfloat16 g_Vth[ELEMS], g_Vtl[ELEMS];
__device__ __nv_bfloat16 g_Ah[ELEMS],  g_Al[ELEMS];     // attn hi/lo
__device__ __nv_bfloat16 g_AVh[ELEMS], g_AVl[ELEMS];
__device__ float g_Sq[BS], g_Tq[BS], g_Sk[BS], g_Tk[BS];

// ============================================================================
// Entropy stats: Sq[r]=sum exp(tanh(q[r,m])), Tq[r]=sum x*exp(x), m<8
// ============================================================================
__global__ void stats_kernel(const float* __restrict__ q, const float* __restrict__ k,
                             float* __restrict__ Sq, float* __restrict__ Tq,
                             float* __restrict__ Sk, float* __restrict__ Tk)
{
    int r = blockIdx.x * blockDim.x + threadIdx.x;
    if (r >= BS) return;
    float s = 0.f, t = 0.f;
    #pragma unroll
    for (int m = 0; m < 8; m++) {
        float x = tanhf(q[(size_t)r * DD + m]);
        float e = expf(x);
        s += e; t += x * e;
    }
    Sq[r] = s; Tq[r] = t;
    s = 0.f; t = 0.f;
    #pragma unroll
    for (int m = 0; m < 8; m++) {
        float x = tanhf(k[(size_t)r * DD + m]);
        float e = expf(x);
        s += e; t += x * e;
    }
    Sk[r] = s; Tk[r] = t;
}

// ============================================================================
// fp32 -> (hi, lo) bf16 split
// ============================================================================
__global__ void convert_kernel(const float* __restrict__ x,
                               __nv_bfloat16* __restrict__ hi,
                               __nv_bfloat16* __restrict__ lo, int n)
{
    int i = (blockIdx.x * blockDim.x + threadIdx.x) * 4;
    if (i >= n) return;
    float4 v = *reinterpret_cast<const float4*>(x + i);
    float f[4] = {v.x, v.y, v.z, v.w};
    #pragma unroll
    for (int j = 0; j < 4; j++) {
        __nv_bfloat16 h = __float2bfloat16(f[j]);
        hi[i + j] = h;
        lo[i + j] = __float2bfloat16(f[j] - __bfloat162float(h));
    }
}

// ============================================================================
// bf16 [S,D] -> [D,S] transpose per batch
// ============================================================================
__global__ void transpose_kernel(const __nv_bfloat16* __restrict__ src,
                                 __nv_bfloat16* __restrict__ dst)
{
    __shared__ __nv_bfloat16 t[32][33];
    int b = blockIdx.z;
    const __nv_bfloat16* s = src + (size_t)b * SS * DD;
    __nv_bfloat16* d = dst + (size_t)b * SS * DD;
    int d0 = blockIdx.x * 32, s0 = blockIdx.y * 32;
    #pragma unroll
    for (int i = threadIdx.y; i < 32; i += 8)
        t[i][threadIdx.x] = s[(size_t)(s0 + i) * DD + d0 + threadIdx.x];
    __syncthreads();
    #pragma unroll
    for (int i = threadIdx.y; i < 32; i += 8)
        d[(size_t)(d0 + i) * SS + s0 + threadIdx.x] = t[threadIdx.x][i];
}

// ============================================================================
// split-bf16 GEMM via mma.sync (HMMA):
//   C[M,N] = sum_K (Ah+Al)(Bh+Bl)^T  (lo*lo dropped)
// A: [M,K] row-major bf16 hi/lo; B: [N,K] row-major bf16 hi/lo.
// Epilogue: Cf (fp32, +bias) and/or Ch/Cl (bf16 split, +bias).
// 256 threads = 8 warps, warp tile 64x32 (warp grid 2m x 4n).
// ============================================================================
__global__ __launch_bounds__(256, 1)
void tc_gemm(const __nv_bfloat16* __restrict__ Ah, const __nv_bfloat16* __restrict__ Al, int lda,
             const __nv_bfloat16* __restrict__ Bh, const __nv_bfloat16* __restrict__ Bl, int ldb,
             const float* __restrict__ bias,
             float* __restrict__ Cf,
             __nv_bfloat16* __restrict__ Ch, __nv_bfloat16* __restrict__ Cl, int ldc,
             int K, long sA, long sB, long sC)
{
    extern __shared__ char smem[];
    const uint32_t sbase = smem_to_u32(smem);

    const int tid  = threadIdx.x;
    const int lane = tid & 31;
    const int wid  = tid >> 5;
    const int wm = (wid & 1) * 64;      // warp m offset in CTA tile
    const int wn = (wid >> 1) * 32;     // warp n offset
    const int rowBase = blockIdx.y * BM;
    const int colBase = blockIdx.x * BN;

    // per-tile global sources (rows already offset by tile base)
    const __nv_bfloat16* gsrc[4];
    gsrc[0] = Ah + (long)blockIdx.z * sA + (long)rowBase * lda;
    gsrc[1] = Al + (long)blockIdx.z * sA + (long)rowBase * lda;
    gsrc[2] = Bh + (long)blockIdx.z * sB + (long)colBase * ldb;
    gsrc[3] = Bl + (long)blockIdx.z * sB + (long)colBase * ldb;
    const int glds[4] = {lda, lda, ldb, ldb};

    const int r0f = tid >> 2;           // fill row for i=0 (lin = tid)
    const int r1f = (tid + 256) >> 2;   // fill row for i=1
    const int segf = tid & 3;

    float acc[4][4][4];
    #pragma unroll
    for (int mf = 0; mf < 4; mf++)
        #pragma unroll
        for (int nf = 0; nf < 4; nf++)
            #pragma unroll
            for (int j = 0; j < 4; j++) acc[mf][nf][j] = 0.f;

    // ---- chunk 0: direct load + store ----
    #pragma unroll
    for (int t = 0; t < 4; t++) {
        uint4 v0 = *reinterpret_cast<const uint4*>(gsrc[t] + (long)r0f * glds[t] + segf * 8);
        uint4 v1 = *reinterpret_cast<const uint4*>(gsrc[t] + (long)r1f * glds[t] + segf * 8);
        sts16(sbase + t * TILE_B + (uint32_t)(r0f * 80 + segf * 16), v0);
        sts16(sbase + t * TILE_B + (uint32_t)(r1f * 80 + segf * 16), v1);
    }
    __syncthreads();

    const int nch = K / BK;
    for (int c = 0; c < nch; c++) {
        const uint32_t st = sbase + (uint32_t)(c & 1) * STAGE_B;

        // prefetch next chunk into registers
        uint4 pf[4][2];
        if (c + 1 < nch) {
            const int k0 = (c + 1) * BK;
            #pragma unroll
            for (int t = 0; t < 4; t++) {
                pf[t][0] = *reinterpret_cast<const uint4*>(gsrc[t] + (long)r0f * glds[t] + k0 + segf * 8);
                pf[t][1] = *reinterpret_cast<const uint4*>(gsrc[t] + (long)r1f * glds[t] + k0 + segf * 8);
            }
        }

        // compute current chunk: 2 k16 steps
        #pragma unroll
        for (int ks = 0; ks < 2; ks++) {
            uint32_t ah[4][4], alr[4][4], bh[4][2], blr[4][2];
            const uint32_t aoff = st +
                (uint32_t)((wm + (lane & 15)) * 80 + (ks * 16 + (lane >> 4) * 8) * 2);
            #pragma unroll
            for (int mf = 0; mf < 4; mf++) {
                ldsm4(ah[mf],  aoff + (uint32_t)(mf * 16 * 80));
                ldsm4(alr[mf], aoff + TILE_B + (uint32_t)(mf * 16 * 80));
            }
            const uint32_t boff = st + 2 * TILE_B +
                (uint32_t)((wn + (lane & 7)) * 80 + (ks * 16 + ((lane >> 3) & 1) * 8) * 2);
            #pragma unroll
            for (int nf = 0; nf < 4; nf++) {
                ldsm2(bh[nf],  boff + (uint32_t)(nf * 8 * 80));
                ldsm2(blr[nf], boff + TILE_B + (uint32_t)(nf * 8 * 80));
            }
            #pragma unroll
            for (int mf = 0; mf < 4; mf++)
                #pragma unroll
                for (int nf = 0; nf < 4; nf++) {
                    mma_bf16(acc[mf][nf], ah[mf],  bh[nf]);
                    mma_bf16(acc[mf][nf], ah[mf],  blr[nf]);
                    mma_bf16(acc[mf][nf], alr[mf], bh[nf]);
                }
        }

        if (c + 1 < nch) {
            __syncthreads();   // everyone done reading the other stage
            const uint32_t stn = sbase + (uint32_t)((c + 1) & 1) * STAGE_B;
            #pragma unroll
            for (int t = 0; t < 4; t++) {
                sts16(stn + t * TILE_B + (uint32_t)(r0f * 80 + segf * 16), pf[t][0]);
                sts16(stn + t * TILE_B + (uint32_t)(r1f * 80 + segf * 16), pf[t][1]);
            }
            __syncthreads();
        }
    }

    // ---- epilogue ----
    float* Cfb = Cf ? Cf + (long)blockIdx.z * sC : nullptr;
    __nv_bfloat16* Chb = Ch ? Ch + (long)blockIdx.z * sC : nullptr;
    __nv_bfloat16* Clb = Cl ? Cl + (long)blockIdx.z * sC : nullptr;

    #pragma unroll
    for (int mf = 0; mf < 4; mf++) {
        #pragma unroll
        for (int nf = 0; nf < 4; nf++) {
            const int r0 = rowBase + wm + mf * 16 + (lane >> 2);
            const int c0 = colBase + wn + nf * 8 + 2 * (lane & 3);
            const float b0 = bias ? bias[c0] : 0.f;
            const float b1 = bias ? bias[c0 + 1] : 0.f;
            const float v00 = acc[mf][nf][0] + b0;
            const float v01 = acc[mf][nf][1] + b1;
            const float v10 = acc[mf][nf][2] + b0;
            const float v11 = acc[mf][nf][3] + b1;
            if (Cfb) {
                float2 u0 = make_float2(v00, v01);
                float2 u1 = make_float2(v10, v11);
                *reinterpret_cast<float2*>(&Cfb[(long)r0 * ldc + c0]) = u0;
                *reinterpret_cast<float2*>(&Cfb[(long)(r0 + 8) * ldc + c0]) = u1;
            }
            if (Chb) {
                __nv_bfloat16 h;
                h = __float2bfloat16(v00);
                Chb[(long)r0 * ldc + c0] = h;
                Clb[(long)r0 * ldc + c0] = __float2bfloat16(v00 - __bfloat162float(h));
                h = __float2bfloat16(v01);
                Chb[(long)r0 * ldc + c0 + 1] = h;
                Clb[(long)r0 * ldc + c0 + 1] = __float2bfloat16(v01 - __bfloat162float(h));
                h = __float2bfloat16(v10);
                Chb[(long)(r0 + 8) * ldc + c0] = h;
                Clb[(long)(r0 + 8) * ldc + c0] = __float2bfloat16(v10 - __bfloat162float(h));
                h = __float2bfloat16(v11);
                Chb[(long)(r0 + 8) * ldc + c0 + 1] = h;
                Clb[(long)(r0 + 8) * ldc + c0 + 1] = __float2bfloat16(v11 - __bfloat162float(h));
            }
        }
    }
}

// ============================================================================
// fused combined + softmax (in-place fp32) + bf16 hi/lo output for attn@V
// combined = 0.7*score/128 + 0.3*(log(Z) - (Tq+Tk)/Z - 1.6e-7), Z = Sq_i + Sk_j
// ============================================================================
__global__ __launch_bounds__(256)
void softmax_kernel(float* __restrict__ attn,
                    __nv_bfloat16* __restrict__ ahi, __nv_bfloat16* __restrict__ alo,
                    const float* __restrict__ Sq, const float* __restrict__ Tq,
                    const float* __restrict__ Sk, const float* __restrict__ Tk)
{
    const int row = blockIdx.x;      // 0..4095
    const int b = row >> 10;
    float* a = attn + (size_t)row * SS;
    __nv_bfloat16* ah = ahi + (size_t)row * SS;
    __nv_bfloat16* al = alo + (size_t)row * SS;
    const float sq = Sq[row], tq = Tq[row];
    const float* skb = Sk + b * SS;
    const float* tkb = Tk + b * SS;
    const int tid = threadIdx.x;

    float c[4];
    float mx = -1e30f;
    #pragma unroll
    for (int u = 0; u < 4; u++) {
        int j = tid + u * 256;
        float Z = sq + skb[j];
        float ent = __logf(Z) - (tq + tkb[j]) / Z - 1.6e-7f;
        float v = 0.7f * (a[j] * (1.0f / 128.0f)) + 0.3f * ent;
        c[u] = v;
        mx = fmaxf(mx, v);
    }

    __shared__ float red[256];
    red[tid] = mx;
    __syncthreads();
    for (int s = 128; s > 0; s >>= 1) {
        if (tid < s) red[tid] = fmaxf(red[tid], red[tid + s]);
        __syncthreads();
    }
    mx = red[0];
    __syncthreads();

    float sum = 0.f;
    #pragma unroll
    for (int u = 0; u < 4; u++) {
        c[u] = __expf(c[u] - mx);
        sum += c[u];
    }
    red[tid] = sum;
    __syncthreads();
    for (int s = 128; s > 0; s >>= 1) {
        if (tid < s) red[tid] += red[tid + s];
        __syncthreads();
    }
    const float inv = 1.0f / red[0];

    #pragma unroll
    for (int u = 0; u < 4; u++) {
        int j = tid + u * 256;
        float f = c[u] * inv;
        a[j] = f;
        __nv_bfloat16 h = __float2bfloat16(f);
        ah[j] = h;
        al[j] = __float2bfloat16(f - __bfloat162float(h));
    }
}

// ============================================================================
// launch
// ============================================================================
extern "C" void kernel_launch(void* const* d_in, const int* in_sizes, int n_in,
                              void* d_out, int out_size)
{
    const float* query = (const float*)d_in[0];
    const float* key   = (const float*)d_in[1];
    const float* value = (const float*)d_in[2];
    const float* Wq = (const float*)d_in[3];
    const float* bq = (const float*)d_in[4];
    const float* Wk = (const float*)d_in[5];
    const float* bk = (const float*)d_in[6];
    const float* Wv = (const float*)d_in[7];
    const float* bv = (const float*)d_in[8];
    const float* Wo = (const float*)d_in[9];
    const float* bo = (const float*)d_in[10];

    float* out  = (float*)d_out;            // [B,S,D]
    float* attn = out + ELEMS;              // [B,S,S]

    cudaFuncSetAttribute(tc_gemm, cudaFuncAttributeMaxDynamicSharedMemorySize, SMEM_REQ);

    auto sym = [](const void* s) {
        void* p = nullptr;
        cudaGetSymbolAddress(&p, s);
        return p;
    };
    __nv_bfloat16* qih = (__nv_bfloat16*)sym(g_qih); __nv_bfloat16* qil = (__nv_bfloat16*)sym(g_qil);
    __nv_bfloat16* kih = (__nv_bfloat16*)sym(g_kih); __nv_bfloat16* kil = (__nv_bfloat16*)sym(g_kil);
    __nv_bfloat16* vih = (__nv_bfloat16*)sym(g_vih); __nv_bfloat16* vil = (__nv_bfloat16*)sym(g_vil);
    __nv_bfloat16* Wqh = (__nv_bfloat16*)sym(g_Wqh); __nv_bfloat16* Wql = (__nv_bfloat16*)sym(g_Wql);
    __nv_bfloat16* Wkh = (__nv_bfloat16*)sym(g_Wkh); __nv_bfloat16* Wkl = (__nv_bfloat16*)sym(g_Wkl);
    __nv_bfloat16* Wvh = (__nv_bfloat16*)sym(g_Wvh); __nv_bfloat16* Wvl = (__nv_bfloat16*)sym(g_Wvl);
    __nv_bfloat16* Woh = (__nv_bfloat16*)sym(g_Woh); __nv_bfloat16* Wol = (__nv_bfloat16*)sym(g_Wol);
    __nv_bfloat16* Qh  = (__nv_bfloat16*)sym(g_Qh);  __nv_bfloat16* Ql  = (__nv_bfloat16*)sym(g_Ql);
    __nv_bfloat16* Kh  = (__nv_bfloat16*)sym(g_Kh);  __nv_bfloat16* Kl  = (__nv_bfloat16*)sym(g_Kl);
    __nv_bfloat16* Vh  = (__nv_bfloat16*)sym(g_Vh);  __nv_bfloat16* Vl  = (__nv_bfloat16*)sym(g_Vl);
    __nv_bfloat16* Vth = (__nv_bfloat16*)sym(g_Vth); __nv_bfloat16* Vtl = (__nv_bfloat16*)sym(g_Vtl);
    __nv_bfloat16* Ahh = (__nv_bfloat16*)sym(g_Ah);  __nv_bfloat16* All = (__nv_bfloat16*)sym(g_Al);
    __nv_bfloat16* AVh = (__nv_bfloat16*)sym(g_AVh); __nv_bfloat16* AVl = (__nv_bfloat16*)sym(g_AVl);
    float* pSq = (float*)sym(g_Sq); float* pTq = (float*)sym(g_Tq);
    float* pSk = (float*)sym(g_Sk); float* pTk = (float*)sym(g_Tk);

    // 1) entropy stats + input/weight splits
    stats_kernel<<<BS / 256, 256>>>(query, key, pSq, pTq, pSk, pTk);
    const int NE = (int)ELEMS, NW = DD * DD;
    convert_kernel<<<NE / 1024, 256>>>(query, qih, qil, NE);
    convert_kernel<<<NE / 1024, 256>>>(key,   kih, kil, NE);
    convert_kernel<<<NE / 1024, 256>>>(value, vih, vil, NE);
    convert_kernel<<<NW / 1024, 256>>>(Wq, Wqh, Wql, NW);
    convert_kernel<<<NW / 1024, 256>>>(Wk, Wkh, Wkl, NW);
    convert_kernel<<<NW / 1024, 256>>>(Wv, Wvh, Wvl, NW);
    convert_kernel<<<NW / 1024, 256>>>(Wo, Woh, Wol, NW);

    // 2) projections: X @ W^T + b   (M=4096, N=1024, K=1024)
    dim3 gp(DD / BN, BS / BM, 1);
    tc_gemm<<<gp, 256, SMEM_REQ>>>(qih, qil, DD, Wqh, Wql, DD, bq,
                                   nullptr, Qh, Ql, DD, DD, 0, 0, 0);
    tc_gemm<<<gp, 256, SMEM_REQ>>>(kih, kil, DD, Wkh, Wkl, DD, bk,
                                   nullptr, Kh, Kl, DD, DD, 0, 0, 0);
    tc_gemm<<<gp, 256, SMEM_REQ>>>(vih, vil, DD, Wvh, Wvl, DD, bv,
                                   nullptr, Vh, Vl, DD, DD, 0, 0, 0);

    // 3) V^T for attn@V B-operand ([N=d, K=t] row-major)
    dim3 gt(DD / 32, SS / 32, BB);
    transpose_kernel<<<gt, dim3(32, 8)>>>(Vh, Vth);
    transpose_kernel<<<gt, dim3(32, 8)>>>(Vl, Vtl);

    // 4) scores S = Q @ K^T per batch -> fp32 into attn buffer
    dim3 gs(SS / BN, SS / BM, BB);
    tc_gemm<<<gs, 256, SMEM_REQ>>>(Qh, Ql, DD, Kh, Kl, DD, nullptr,
                                   attn, nullptr, nullptr, SS,
                                   DD, (long)SS * DD, (long)SS * DD, (long)SS * SS);

    // 5) fused combined + softmax (in place) + bf16 split attn
    softmax_kernel<<<BS, 256>>>(attn, Ahh, All, pSq, pTq, pSk, pTk);

    // 6) AV = attn @ V per batch (B = V^T, K-major over t)
    tc_gemm<<<gs, 256, SMEM_REQ>>>(Ahh, All, SS, Vth, Vtl, SS, nullptr,
                                   nullptr, AVh, AVl, DD,
                                   SS, (long)SS * SS, (long)SS * DD, (long)SS * DD);

    // 7) output = AV @ Wo^T + bo
    tc_gemm<<<gp, 256, SMEM_REQ>>>(AVh, AVl, DD, Woh, Wol, DD, bo,
                                   out, nullptr, nullptr, DD, DD, 0, 0, 0);
}

// round 9
// speedup vs baseline: 2.1904x; 1.1048x over previous
#include <cuda_runtime.h>
#include <cuda_bf16.h>
#include <cstdint>
#include <math.h>

// Problem constants
#define BB 4
#define SS 1024
#define DD 1024
#define BS (BB*SS)                  // 4096 rows total
#define ELEMS ((size_t)BB*SS*DD)    // 4194304  (== B*S*S too)
#define NW (DD*DD)

// ============================================================================
// GEMM tiling
// ============================================================================
#define BM 128
#define BN 128
#define BK 32
#define ASTRIDE 40                      // bf16 elems per smem row (80 bytes)
#define TILE_B (128*ASTRIDE*2)          // 10240 bytes per tile (128 rows x 80B)
#define STAGE_B (4*TILE_B)              // Ah, Al, Bh, Bl = 40960 B
#define NSTAGE 3
#define SMEM_REQ (NSTAGE*STAGE_B)       // 122880 B

__device__ __forceinline__ uint32_t smem_to_u32(const void* smem_ptr) {
    uint32_t addr;
    asm("{ .reg .u64 tmp; cvta.to.shared.u64 tmp, %1; cvt.u32.u64 %0, tmp; }"
        : "=r"(addr) : "l"(smem_ptr));
    return addr;
}
__device__ __forceinline__ void ldsm4(uint32_t* r, uint32_t addr) {
    asm volatile("ldmatrix.sync.aligned.m8n8.x4.shared.b16 {%0,%1,%2,%3}, [%4];"
                 : "=r"(r[0]), "=r"(r[1]), "=r"(r[2]), "=r"(r[3]) : "r"(addr));
}
__device__ __forceinline__ void ldsm2(uint32_t* r, uint32_t addr) {
    asm volatile("ldmatrix.sync.aligned.m8n8.x2.shared.b16 {%0,%1}, [%2];"
                 : "=r"(r[0]), "=r"(r[1]) : "r"(addr));
}
__device__ __forceinline__ void mma_bf16(float* c, const uint32_t* a, const uint32_t* b) {
    asm volatile(
        "mma.sync.aligned.m16n8k16.row.col.f32.bf16.bf16.f32 "
        "{%0,%1,%2,%3}, {%4,%5,%6,%7}, {%8,%9}, {%0,%1,%2,%3};"
        : "+f"(c[0]), "+f"(c[1]), "+f"(c[2]), "+f"(c[3])
        : "r"(a[0]), "r"(a[1]), "r"(a[2]), "r"(a[3]), "r"(b[0]), "r"(b[1]));
}
__device__ __forceinline__ void cp_async16(uint32_t dst, const void* src) {
    asm volatile("cp.async.cg.shared.global [%0], [%1], 16;" :: "r"(dst), "l"(src));
}
#define CP_COMMIT() asm volatile("cp.async.commit_group;" ::: "memory")
#define CP_WAIT1()  asm volatile("cp.async.wait_group 1;" ::: "memory")

// ============================================================================
// Scratch (no allocation allowed) — merged contiguous regions for z-batching
// ============================================================================
__device__ __nv_bfloat16 g_Xh[3*ELEMS], g_Xl[3*ELEMS];   // q,k,v inputs split
__device__ __nv_bfloat16 g_Wh[4*NW],    g_Wl[4*NW];      // Wq,Wk,Wv,Wo split
__device__ __nv_bfloat16 g_Ph[3*ELEMS], g_Pl[3*ELEMS];   // Q,K,V projections split
__device__ __nv_bfloat16 g_Vth[ELEMS],  g_Vtl[ELEMS];    // V^T split
__device__ __nv_bfloat16 g_Ah[ELEMS],   g_Al[ELEMS];     // attn split
__device__ __nv_bfloat16 g_AVh[ELEMS],  g_AVl[ELEMS];    // attn@V split
__device__ float g_Sq[BS], g_Tq[BS], g_Sk[BS], g_Tk[BS];

// ============================================================================
// Entropy stats: Sq[r]=sum exp(tanh(q[r,m])), Tq[r]=sum x*exp(x), m<8
// ============================================================================
__global__ void stats_kernel(const float* __restrict__ q, const float* __restrict__ k,
                             float* __restrict__ Sq, float* __restrict__ Tq,
                             float* __restrict__ Sk, float* __restrict__ Tk)
{
    int r = blockIdx.x * blockDim.x + threadIdx.x;
    if (r >= BS) return;
    float s = 0.f, t = 0.f;
    #pragma unroll
    for (int m = 0; m < 8; m++) {
        float x = tanhf(q[(size_t)r * DD + m]);
        float e = expf(x);
        s += e; t += x * e;
    }
    Sq[r] = s; Tq[r] = t;
    s = 0.f; t = 0.f;
    #pragma unroll
    for (int m = 0; m < 8; m++) {
        float x = tanhf(k[(size_t)r * DD + m]);
        float e = expf(x);
        s += e; t += x * e;
    }
    Sk[r] = s; Tk[r] = t;
}

// ============================================================================
// fp32 -> (hi, lo) bf16 split; z selects one of up to 4 sources
// ============================================================================
__global__ void convert_kernel(const float* __restrict__ x0, const float* __restrict__ x1,
                               const float* __restrict__ x2, const float* __restrict__ x3,
                               __nv_bfloat16* __restrict__ hi,
                               __nv_bfloat16* __restrict__ lo, int n)
{
    const int z = blockIdx.z;
    const float* x = (z == 0) ? x0 : (z == 1) ? x1 : (z == 2) ? x2 : x3;
    __nv_bfloat16* h = hi + (size_t)z * n;
    __nv_bfloat16* l = lo + (size_t)z * n;
    int i = (blockIdx.x * blockDim.x + threadIdx.x) * 4;
    if (i >= n) return;
    float4 v = *reinterpret_cast<const float4*>(x + i);
    float f[4] = {v.x, v.y, v.z, v.w};
    __nv_bfloat16 hh[4], ll[4];
    #pragma unroll
    for (int j = 0; j < 4; j++) {
        hh[j] = __float2bfloat16(f[j]);
        ll[j] = __float2bfloat16(f[j] - __bfloat162float(hh[j]));
    }
    *reinterpret_cast<uint2*>(h + i) = *reinterpret_cast<uint2*>(hh);
    *reinterpret_cast<uint2*>(l + i) = *reinterpret_cast<uint2*>(ll);
}

// ============================================================================
// bf16 [S,D] -> [D,S] transpose per batch; z = part*BB + b, part picks hi/lo
// ============================================================================
__global__ void transpose_kernel(const __nv_bfloat16* __restrict__ srcH,
                                 const __nv_bfloat16* __restrict__ srcL,
                                 __nv_bfloat16* __restrict__ dstH,
                                 __nv_bfloat16* __restrict__ dstL)
{
    __shared__ __nv_bfloat16 t[32][33];
    const int z = blockIdx.z;
    const int b = z & (BB - 1), part = z >> 2;
    const __nv_bfloat16* s = (part ? srcL : srcH) + (size_t)b * SS * DD;
    __nv_bfloat16* d = (part ? dstL : dstH) + (size_t)b * SS * DD;
    int d0 = blockIdx.x * 32, s0 = blockIdx.y * 32;
    #pragma unroll
    for (int i = threadIdx.y; i < 32; i += 8)
        t[i][threadIdx.x] = s[(size_t)(s0 + i) * DD + d0 + threadIdx.x];
    __syncthreads();
    #pragma unroll
    for (int i = threadIdx.y; i < 32; i += 8)
        d[(size_t)(d0 + i) * SS + s0 + threadIdx.x] = t[threadIdx.x][i];
}

// ============================================================================
// split-bf16 GEMM via mma.sync + cp.async 3-stage pipeline:
//   C[M,N] = sum_K (Ah+Al)(Bh+Bl)^T  (lo*lo dropped)
// A: [M,K] row-major bf16 hi/lo; B: [N,K] row-major bf16 hi/lo.
// Epilogue: Cf (fp32, +bias) and/or Ch/Cl (bf16 split, +bias).
// 256 threads = 8 warps, warp tile 64x32 (warp grid 2m x 4n).
// biasByZ: select bias0/1/2 by blockIdx.z (fused QKV projections).
// ============================================================================
__global__ __launch_bounds__(256, 1)
void tc_gemm(const __nv_bfloat16* __restrict__ Ah, const __nv_bfloat16* __restrict__ Al, int lda,
             const __nv_bfloat16* __restrict__ Bh, const __nv_bfloat16* __restrict__ Bl, int ldb,
             const float* __restrict__ bias0, const float* __restrict__ bias1,
             const float* __restrict__ bias2, int biasByZ,
             float* __restrict__ Cf,
             __nv_bfloat16* __restrict__ Ch, __nv_bfloat16* __restrict__ Cl, int ldc,
             int K, long sA, long sB, long sC)
{
    extern __shared__ char smem[];
    const uint32_t sbase = smem_to_u32(smem);

    const int tid  = threadIdx.x;
    const int lane = tid & 31;
    const int wid  = tid >> 5;
    const int wm = (wid & 1) * 64;      // warp m offset in CTA tile
    const int wn = (wid >> 1) * 32;     // warp n offset
    const int rowBase = blockIdx.y * BM;
    const int colBase = blockIdx.x * BN;
    const int z = blockIdx.z;

    const float* bias = biasByZ ? ((z == 0) ? bias0 : (z == 1) ? bias1 : bias2) : bias0;

    const __nv_bfloat16* gsrc[4];
    gsrc[0] = Ah + (long)z * sA + (long)rowBase * lda;
    gsrc[1] = Al + (long)z * sA + (long)rowBase * lda;
    gsrc[2] = Bh + (long)z * sB + (long)colBase * ldb;
    gsrc[3] = Bl + (long)z * sB + (long)colBase * ldb;
    const int glds[4] = {lda, lda, ldb, ldb};

    const int r0f = tid >> 2;           // row for entry 0
    const int r1f = (tid + 256) >> 2;   // row for entry 1
    const int segf = tid & 3;

    float acc[4][4][4];
    #pragma unroll
    for (int mf = 0; mf < 4; mf++)
        #pragma unroll
        for (int nf = 0; nf < 4; nf++)
            #pragma unroll
            for (int j = 0; j < 4; j++) acc[mf][nf][j] = 0.f;

    // stage fill via cp.async (each thread: 2 x 16B per tile, 4 tiles)
    auto issue_stage = [&](int stage, int k0) {
        const uint32_t st = sbase + (uint32_t)stage * STAGE_B;
        #pragma unroll
        for (int t = 0; t < 4; t++) {
            cp_async16(st + (uint32_t)(t * TILE_B + r0f * 80 + segf * 16),
                       gsrc[t] + (long)r0f * glds[t] + k0 + segf * 8);
            cp_async16(st + (uint32_t)(t * TILE_B + r1f * 80 + segf * 16),
                       gsrc[t] + (long)r1f * glds[t] + k0 + segf * 8);
        }
    };

    issue_stage(0, 0);  CP_COMMIT();
    issue_stage(1, BK); CP_COMMIT();

    const int nch = K / BK;
    for (int c = 0; c < nch; c++) {
        CP_WAIT1();             // group for stage c retired (2 groups in flight max)
        __syncthreads();        // stage-c data visible; stage (c+2)%3 free to refill

        if (c + 2 < nch) issue_stage((c + 2) % NSTAGE, (c + 2) * BK);
        CP_COMMIT();            // always commit (empty groups keep the count in step)

        const uint32_t st = sbase + (uint32_t)(c % NSTAGE) * STAGE_B;
        #pragma unroll
        for (int ks = 0; ks < 2; ks++) {
            uint32_t ah[4][4], alr[4][4], bh[4][2], blr[4][2];
            const uint32_t aoff = st +
                (uint32_t)((wm + (lane & 15)) * 80 + (ks * 16 + (lane >> 4) * 8) * 2);
            #pragma unroll
            for (int mf = 0; mf < 4; mf++) {
                ldsm4(ah[mf],  aoff + (uint32_t)(mf * 16 * 80));
                ldsm4(alr[mf], aoff + TILE_B + (uint32_t)(mf * 16 * 80));
            }
            const uint32_t boff = st + 2 * TILE_B +
                (uint32_t)((wn + (lane & 7)) * 80 + (ks * 16 + ((lane >> 3) & 1) * 8) * 2);
            #pragma unroll
            for (int nf = 0; nf < 4; nf++) {
                ldsm2(bh[nf],  boff + (uint32_t)(nf * 8 * 80));
                ldsm2(blr[nf], boff + TILE_B + (uint32_t)(nf * 8 * 80));
            }
            #pragma unroll
            for (int mf = 0; mf < 4; mf++)
                #pragma unroll
                for (int nf = 0; nf < 4; nf++) {
                    mma_bf16(acc[mf][nf], ah[mf],  bh[nf]);
                    mma_bf16(acc[mf][nf], ah[mf],  blr[nf]);
                    mma_bf16(acc[mf][nf], alr[mf], bh[nf]);
                }
        }
    }

    // ---- epilogue ----
    float* Cfb = Cf ? Cf + (long)z * sC : nullptr;
    __nv_bfloat16* Chb = Ch ? Ch + (long)z * sC : nullptr;
    __nv_bfloat16* Clb = Cl ? Cl + (long)z * sC : nullptr;

    #pragma unroll
    for (int mf = 0; mf < 4; mf++) {
        #pragma unroll
        for (int nf = 0; nf < 4; nf++) {
            const int r0 = rowBase + wm + mf * 16 + (lane >> 2);
            const int c0 = colBase + wn + nf * 8 + 2 * (lane & 3);
            const float b0 = bias ? bias[c0] : 0.f;
            const float b1 = bias ? bias[c0 + 1] : 0.f;
            const float v00 = acc[mf][nf][0] + b0;
            const float v01 = acc[mf][nf][1] + b1;
            const float v10 = acc[mf][nf][2] + b0;
            const float v11 = acc[mf][nf][3] + b1;
            if (Cfb) {
                *reinterpret_cast<float2*>(&Cfb[(long)r0 * ldc + c0]) = make_float2(v00, v01);
                *reinterpret_cast<float2*>(&Cfb[(long)(r0 + 8) * ldc + c0]) = make_float2(v10, v11);
            }
            if (Chb) {
                __nv_bfloat162 h2, l2;
                h2.x = __float2bfloat16(v00);
                h2.y = __float2bfloat16(v01);
                l2.x = __float2bfloat16(v00 - __bfloat162float(h2.x));
                l2.y = __float2bfloat16(v01 - __bfloat162float(h2.y));
                *reinterpret_cast<__nv_bfloat162*>(&Chb[(long)r0 * ldc + c0]) = h2;
                *reinterpret_cast<__nv_bfloat162*>(&Clb[(long)r0 * ldc + c0]) = l2;
                h2.x = __float2bfloat16(v10);
                h2.y = __float2bfloat16(v11);
                l2.x = __float2bfloat16(v10 - __bfloat162float(h2.x));
                l2.y = __float2bfloat16(v11 - __bfloat162float(h2.y));
                *reinterpret_cast<__nv_bfloat162*>(&Chb[(long)(r0 + 8) * ldc + c0]) = h2;
                *reinterpret_cast<__nv_bfloat162*>(&Clb[(long)(r0 + 8) * ldc + c0]) = l2;
            }
        }
    }
}

// ============================================================================
// fused combined + softmax (in-place fp32) + bf16 hi/lo output for attn@V
// combined = 0.7*score/128 + 0.3*(log(Z) - (Tq+Tk)/Z - 1.6e-7), Z = Sq_i + Sk_j
// ============================================================================
__global__ __launch_bounds__(256)
void softmax_kernel(float* __restrict__ attn,
                    __nv_bfloat16* __restrict__ ahi, __nv_bfloat16* __restrict__ alo,
                    const float* __restrict__ Sq, const float* __restrict__ Tq,
                    const float* __restrict__ Sk, const float* __restrict__ Tk)
{
    const int row = blockIdx.x;      // 0..4095
    const int b = row >> 10;
    float* a = attn + (size_t)row * SS;
    __nv_bfloat16* ah = ahi + (size_t)row * SS;
    __nv_bfloat16* al = alo + (size_t)row * SS;
    const float sq = Sq[row], tq = Tq[row];
    const float* skb = Sk + b * SS;
    const float* tkb = Tk + b * SS;
    const int tid = threadIdx.x;

    float c[4];
    float mx = -1e30f;
    #pragma unroll
    for (int u = 0; u < 4; u++) {
        int j = tid + u * 256;
        float Z = sq + skb[j];
        float ent = __logf(Z) - (tq + tkb[j]) / Z - 1.6e-7f;
        float v = 0.7f * (a[j] * (1.0f / 128.0f)) + 0.3f * ent;
        c[u] = v;
        mx = fmaxf(mx, v);
    }

    __shared__ float red[256];
    red[tid] = mx;
    __syncthreads();
    for (int s = 128; s > 0; s >>= 1) {
        if (tid < s) red[tid] = fmaxf(red[tid], red[tid + s]);
        __syncthreads();
    }
    mx = red[0];
    __syncthreads();

    float sum = 0.f;
    #pragma unroll
    for (int u = 0; u < 4; u++) {
        c[u] = __expf(c[u] - mx);
        sum += c[u];
    }
    red[tid] = sum;
    __syncthreads();
    for (int s = 128; s > 0; s >>= 1) {
        if (tid < s) red[tid] += red[tid + s];
        __syncthreads();
    }
    const float inv = 1.0f / red[0];

    #pragma unroll
    for (int u = 0; u < 4; u++) {
        int j = tid + u * 256;
        float f = c[u] * inv;
        a[j] = f;
        __nv_bfloat16 h = __float2bfloat16(f);
        ah[j] = h;
        al[j] = __float2bfloat16(f - __bfloat162float(h));
    }
}

// ============================================================================
// launch
// ============================================================================
extern "C" void kernel_launch(void* const* d_in, const int* in_sizes, int n_in,
                              void* d_out, int out_size)
{
    const float* query = (const float*)d_in[0];
    const float* key   = (const float*)d_in[1];
    const float* value = (const float*)d_in[2];
    const float* Wq = (const float*)d_in[3];
    const float* bq = (const float*)d_in[4];
    const float* Wk = (const float*)d_in[5];
    const float* bk = (const float*)d_in[6];
    const float* Wv = (const float*)d_in[7];
    const float* bv = (const float*)d_in[8];
    const float* Wo = (const float*)d_in[9];
    const float* bo = (const float*)d_in[10];

    float* out  = (float*)d_out;            // [B,S,D]
    float* attn = out + ELEMS;              // [B,S,S]

    cudaFuncSetAttribute(tc_gemm, cudaFuncAttributeMaxDynamicSharedMemorySize, SMEM_REQ);

    auto sym = [](const void* s) {
        void* p = nullptr;
        cudaGetSymbolAddress(&p, s);
        return p;
    };
    __nv_bfloat16* Xh  = (__nv_bfloat16*)sym(g_Xh);  __nv_bfloat16* Xl  = (__nv_bfloat16*)sym(g_Xl);
    __nv_bfloat16* Wh  = (__nv_bfloat16*)sym(g_Wh);  __nv_bfloat16* Wl  = (__nv_bfloat16*)sym(g_Wl);
    __nv_bfloat16* Ph  = (__nv_bfloat16*)sym(g_Ph);  __nv_bfloat16* Pl  = (__nv_bfloat16*)sym(g_Pl);
    __nv_bfloat16* Vth = (__nv_bfloat16*)sym(g_Vth); __nv_bfloat16* Vtl = (__nv_bfloat16*)sym(g_Vtl);
    __nv_bfloat16* Ahh = (__nv_bfloat16*)sym(g_Ah);  __nv_bfloat16* All = (__nv_bfloat16*)sym(g_Al);
    __nv_bfloat16* AVh = (__nv_bfloat16*)sym(g_AVh); __nv_bfloat16* AVl = (__nv_bfloat16*)sym(g_AVl);
    float* pSq = (float*)sym(g_Sq); float* pTq = (float*)sym(g_Tq);
    float* pSk = (float*)sym(g_Sk); float* pTk = (float*)sym(g_Tk);

    const int NE = (int)ELEMS;

    // 1) entropy stats + fused input/weight splits
    stats_kernel<<<BS / 256, 256>>>(query, key, pSq, pTq, pSk, pTk);
    convert_kernel<<<dim3(NE / 1024, 1, 3), 256>>>(query, key, value, value, Xh, Xl, NE);
    convert_kernel<<<dim3(NW / 1024, 1, 4), 256>>>(Wq, Wk, Wv, Wo, Wh, Wl, NW);

    // 2) fused Q/K/V projections: X[z] @ W[z]^T + b[z]   (z = 0,1,2)
    dim3 gp(DD / BN, BS / BM, 3);
    tc_gemm<<<gp, 256, SMEM_REQ>>>(Xh, Xl, DD, Wh, Wl, DD, bq, bk, bv, 1,
                                   nullptr, Ph, Pl, DD, DD,
                                   (long)ELEMS, (long)NW, (long)ELEMS);

    // 3) V^T hi+lo in one launch ([N=d, K=t] row-major for attn@V)
    dim3 gt(DD / 32, SS / 32, 2 * BB);
    transpose_kernel<<<gt, dim3(32, 8)>>>(Ph + 2 * ELEMS, Pl + 2 * ELEMS, Vth, Vtl);

    // 4) scores S = Q @ K^T per batch -> fp32 into attn buffer
    dim3 gs(SS / BN, SS / BM, BB);
    tc_gemm<<<gs, 256, SMEM_REQ>>>(Ph, Pl, DD, Ph + ELEMS, Pl + ELEMS, DD,
                                   nullptr, nullptr, nullptr, 0,
                                   attn, nullptr, nullptr, SS,
                                   DD, (long)SS * DD, (long)SS * DD, (long)SS * SS);

    // 5) fused combined + softmax (in place) + bf16 split attn
    softmax_kernel<<<BS, 256>>>(attn, Ahh, All, pSq, pTq, pSk, pTk);

    // 6) AV = attn @ V per batch (B = V^T, K-major over t)
    tc_gemm<<<gs, 256, SMEM_REQ>>>(Ahh, All, SS, Vth, Vtl, SS,
                                   nullptr, nullptr, nullptr, 0,
                                   nullptr, AVh, AVl, DD,
                                   SS, (long)SS * SS, (long)SS * DD, (long)SS * DD);

    // 7) output = AV @ Wo^T + bo
    dim3 go(DD / BN, BS / BM, 1);
    tc_gemm<<<go, 256, SMEM_REQ>>>(AVh, AVl, DD, Wh + 3 * (size_t)NW, Wl + 3 * (size_t)NW, DD,
                                   bo, nullptr, nullptr, 0,
                                   out, nullptr, nullptr, DD, DD, 0, 0, 0);
}